// round 7
// baseline (speedup 1.0000x reference)
#include <cuda_runtime.h>
#include <cstdint>
#include <math.h>

// ---------------------------------------------------------------------------
// 2-layer LSTM (B=64, T=2048, D=64, H=512) + linear head + log_softmax.
//
// Persistent weight-stationary kernel. R7: SPLIT global barrier per layer and
// hide its latency: cntA[t] = h1[t] ready, cntB[t] = h2[t] ready.
// Round r: [L0: wait A[r-1], compute h1[r], publish A[r]]
//          [L1: wait B[r-2], compute h2[r-1], publish B[r-1]].
// A[r] is needed only at round r+1 start (slack = L1 phase ~2/3 round);
// B[r-1] only after round r+1's L0 phase (slack ~1/3 round) -> barrier
// latency + CTA jitter hidden under compute instead of exposed every round.
// Inner loop unchanged from R6 (lane owns 2 batches, LDS.128 weight row-pair
// feeds 4 FFMA2 via fma.rn.f32x2).
// ---------------------------------------------------------------------------

namespace {
constexpr int B_   = 64;
constexpr int T_   = 2048;
constexpr int D_   = 64;
constexpr int H_   = 512;
constexpr int OUT_ = 10;
constexpr int NCTA = 128;
constexpr int NTHR = 512;
constexpr int ROWS = 16;                  // gate rows per layer per CTA
constexpr int K0   = H_ + D_;
constexpr int K1   = H_ + H_;

constexpr size_t OFF_W0  = 0;                                   // [576][16]
constexpr size_t OFF_W1  = OFF_W0 + (size_t)K0 * ROWS * 4;      //  36864
constexpr size_t OFF_GP  = OFF_W1 + (size_t)K1 * ROWS * 4;      // 102400
constexpr size_t OFF_CST = OFF_GP + (size_t)8 * 8 * B_ * 8;     // 135168
constexpr size_t OFF_BIA = OFF_CST + 2048;                      // 137216
constexpr size_t SMEM_BYTES = OFF_BIA + 128;                    // 137344

constexpr int HV_STRIDE = 521;                  // head staging
constexpr size_t OFF_LG = (size_t)B_ * HV_STRIDE * 4;           // 133376
}

// Static device scratch (no runtime allocation).
__device__ float g_h1[(size_t)T_ * H_ * B_];   // layer0 h, [t][unit][b]
__device__ float g_h2[(size_t)T_ * H_ * B_];   // layer1 h, [t][unit][b]
__device__ float g_xT[(size_t)T_ * D_ * B_];   // x transposed, [t][k][b]
__device__ int   g_cntA[T_ + 1];               // h1[t] ready counters
__device__ int   g_cntB[T_ + 1];               // h2[t] ready counters

__device__ __forceinline__ void ffma2(uint64_t& acc, uint64_t a, uint64_t b) {
    asm("fma.rn.f32x2 %0, %1, %2, %0;" : "+l"(acc) : "l"(a), "l"(b));
}
__device__ __forceinline__ void addf2(uint64_t& acc, uint64_t a) {
    asm("add.rn.f32x2 %0, %0, %1;" : "+l"(acc) : "l"(a));
}
__device__ __forceinline__ uint64_t dup2(float x) {
    uint64_t r;
    asm("mov.b64 %0, {%1, %1};" : "=l"(r) : "f"(x));
    return r;
}
__device__ __forceinline__ float2 unpk(uint64_t v) {
    float2 f;
    asm("mov.b64 {%0, %1}, %2;" : "=f"(f.x), "=f"(f.y) : "l"(v));
    return f;
}
__device__ __forceinline__ int ld_acq(const int* p) {
    int v;
    asm volatile("ld.global.acquire.gpu.b32 %0, [%1];" : "=r"(v) : "l"(p));
    return v;
}
__device__ __forceinline__ float fast_sigmoid(float x) {
    return 1.f / (1.f + __expf(-x));
}
__device__ __forceinline__ float fast_tanh(float x) {
    float a = fabsf(x);
    float t = __expf(-2.f * a);
    float r = (1.f - t) / (1.f + t);
    return copysignf(r, x);
}

// acc{A,B}[p] += W[k][2p..2p+1] * in[k][b2(+1)], k in [kb,ke).
__device__ __forceinline__ void gemv2(uint64_t aA[8], uint64_t aB[8],
                                      const float* __restrict__ wsm,
                                      const float* __restrict__ in,
                                      int kb, int ke, int b2) {
#pragma unroll 4
    for (int k = kb; k < ke; ++k) {
        float2 v = *(const float2*)(in + (size_t)k * B_ + b2);
        uint64_t x0 = dup2(v.x);
        uint64_t x1 = dup2(v.y);
        const ulonglong2* wv = (const ulonglong2*)(wsm + (size_t)k * ROWS);
#pragma unroll
        for (int q = 0; q < 4; ++q) {
            ulonglong2 wp = wv[q];
            ffma2(aA[2 * q],     wp.x, x0);
            ffma2(aA[2 * q + 1], wp.y, x0);
            ffma2(aB[2 * q],     wp.x, x1);
            ffma2(aB[2 * q + 1], wp.y, x1);
        }
    }
}

// prep: zero counters + transpose x[b][t][k] -> g_xT[t][k][b]
__global__ void prep_kernel(const float* __restrict__ x) {
    __shared__ float tile[64][65];
    int t = blockIdx.x;
    if (threadIdx.x == 0) {
        g_cntA[t] = 0;
        g_cntB[t] = 0;
        if (t == 0) { g_cntA[T_] = 0; g_cntB[T_] = 0; }
    }
    for (int i = threadIdx.x; i < 64 * 64; i += blockDim.x) {
        int b = i >> 6, k = i & 63;
        tile[b][k] = x[(size_t)b * T_ * D_ + (size_t)t * D_ + k];
    }
    __syncthreads();
    for (int i = threadIdx.x; i < 64 * 64; i += blockDim.x) {
        int k = i >> 6, b = i & 63;
        g_xT[(size_t)t * D_ * B_ + (size_t)k * B_ + b] = tile[b][k];
    }
}

__global__ __launch_bounds__(NTHR, 1)
void lstm_kernel(const float* __restrict__ Wih0, const float* __restrict__ Whh0,
                 const float* __restrict__ bih0, const float* __restrict__ bhh0,
                 const float* __restrict__ Wih1, const float* __restrict__ Whh1,
                 const float* __restrict__ bih1, const float* __restrict__ bhh1,
                 const float* __restrict__ Wlin, const float* __restrict__ blin,
                 float* __restrict__ out) {
    extern __shared__ unsigned char smem[];
    float*    w0   = (float*)(smem + OFF_W0);      // [K0][16]
    float*    w1   = (float*)(smem + OFF_W1);      // [K1][16]
    uint64_t* gp   = (uint64_t*)(smem + OFF_GP);   // [8 slice][8 pair][64 b]
    float*    cst  = (float*)(smem + OFF_CST);     // [2][4][64]
    float*    bias = (float*)(smem + OFF_BIA);     // [2][16]

    const int tid  = threadIdx.x;
    const int lane = tid & 31;
    const int s    = tid >> 5;                     // k-slice 0..15
    const int b2   = 2 * lane;
    const int j0   = blockIdx.x * 4;
    const bool hi  = (s >= 8);
    const int slo  = s & 7;

    // ---- load weights ----
    for (int idx = tid; idx < K0 * ROWS; idx += NTHR) {
        int k = idx >> 4, r = idx & 15;
        int row = (r >> 2) * H_ + j0 + (r & 3);
        w0[idx] = (k < H_) ? Whh0[(size_t)row * H_ + k]
                           : Wih0[(size_t)row * D_ + (k - H_)];
    }
    for (int idx = tid; idx < K1 * ROWS; idx += NTHR) {
        int k = idx >> 4, r = idx & 15;
        int row = (r >> 2) * H_ + j0 + (r & 3);
        w1[idx] = (k < H_) ? Whh1[(size_t)row * H_ + k]
                           : Wih1[(size_t)row * H_ + (k - H_)];
    }
    if (tid < 32) {
        int l = tid >> 4, r = tid & 15;
        int row = (r >> 2) * H_ + j0 + (r & 3);
        bias[tid] = l ? (bih1[row] + bhh1[row]) : (bih0[row] + bhh0[row]);
    }
    cst[tid] = 0.f;
    __syncthreads();

    const float* w0x  = w0 + (size_t)H_ * ROWS;
    const float* w1ff = w1 + (size_t)H_ * ROWS;

    for (int r = 0; r <= T_; ++r) {
        uint64_t aA[8], aB[8];

        // =============== L0 phase: step r (skip at r==T_) ===============
        // (wait A[r-1] was fused into the previous round's tail)
        if (r < T_) {
#pragma unroll
            for (int i = 0; i < 8; ++i) { aA[i] = 0ull; aB[i] = 0ull; }
            if (r >= 1)
                gemv2(aA, aB, w0, g_h1 + (size_t)(r - 1) * H_ * B_,
                      s * 32, s * 32 + 32, b2);
            gemv2(aA, aB, w0x, g_xT + (size_t)r * D_ * B_,
                  s * 4, s * 4 + 4, b2);
            if (hi) {
                ulonglong2* d = (ulonglong2*)(gp + ((size_t)slo * 8) * B_ + b2);
#pragma unroll
                for (int p = 0; p < 8; ++p)
                    d[p * (B_ / 2)] = make_ulonglong2(aA[p], aB[p]);
            }
            __syncthreads();
            if (!hi) {
                ulonglong2* d = (ulonglong2*)(gp + ((size_t)slo * 8) * B_ + b2);
#pragma unroll
                for (int p = 0; p < 8; ++p) {
                    ulonglong2 o = d[p * (B_ / 2)];
                    addf2(aA[p], o.x);
                    addf2(aB[p], o.y);
                    d[p * (B_ / 2)] = make_ulonglong2(aA[p], aB[p]);
                }
            }
            __syncthreads();
            if (tid < 128) {                       // gates layer 0
                int p = tid >> 6, b = tid & 63;
                uint64_t sg[4];
#pragma unroll
                for (int g = 0; g < 4; ++g) {
                    int pi = g * 2 + p;
                    uint64_t v = gp[(size_t)pi * B_ + b];
#pragma unroll
                    for (int ss = 1; ss < 8; ++ss)
                        addf2(v, gp[((size_t)ss * 8 + pi) * B_ + b]);
                    sg[g] = v;
                }
                float2 vi = unpk(sg[0]), vf = unpk(sg[1]);
                float2 vg = unpk(sg[2]), vo = unpk(sg[3]);
#pragma unroll
                for (int j2 = 0; j2 < 2; ++j2) {
                    int j = 2 * p + j2;
                    float gi = (j2 ? vi.y : vi.x) + bias[j];
                    float gf = (j2 ? vf.y : vf.x) + bias[4 + j];
                    float gg = (j2 ? vg.y : vg.x) + bias[8 + j];
                    float go = (j2 ? vo.y : vo.x) + bias[12 + j];
                    float si = fast_sigmoid(gi);
                    float sf = fast_sigmoid(gf);
                    float so = fast_sigmoid(go);
                    float tg = fast_tanh(gg);
                    int ci = j * 64 + b;
                    float c = sf * cst[ci] + si * tg;
                    cst[ci] = c;
                    g_h1[(size_t)r * H_ * B_ + (size_t)(j0 + j) * B_ + b]
                        = so * fast_tanh(c);
                }
            }
        }

        // =============== publish A[r]; wait B[r-2] ===============
        __syncthreads();
        if (tid == 0) {
            if (r < T_) {
                __threadfence();
                atomicAdd(&g_cntA[r], 1);
            }
            if (r >= 2) {
                while (ld_acq(&g_cntB[r - 2]) < NCTA) {}
            }
        }
        __syncthreads();

        // =============== L1 phase: step r-1 (skip at r==0) ===============
        if (r >= 1) {
#pragma unroll
            for (int i = 0; i < 8; ++i) { aA[i] = 0ull; aB[i] = 0ull; }
            gemv2(aA, aB, w1ff, g_h1 + (size_t)(r - 1) * H_ * B_,
                  s * 32, s * 32 + 32, b2);
            if (r >= 2)
                gemv2(aA, aB, w1, g_h2 + (size_t)(r - 2) * H_ * B_,
                      s * 32, s * 32 + 32, b2);
            if (hi) {
                ulonglong2* d = (ulonglong2*)(gp + ((size_t)slo * 8) * B_ + b2);
#pragma unroll
                for (int p = 0; p < 8; ++p)
                    d[p * (B_ / 2)] = make_ulonglong2(aA[p], aB[p]);
            }
            __syncthreads();
            if (!hi) {
                ulonglong2* d = (ulonglong2*)(gp + ((size_t)slo * 8) * B_ + b2);
#pragma unroll
                for (int p = 0; p < 8; ++p) {
                    ulonglong2 o = d[p * (B_ / 2)];
                    addf2(aA[p], o.x);
                    addf2(aB[p], o.y);
                    d[p * (B_ / 2)] = make_ulonglong2(aA[p], aB[p]);
                }
            }
            __syncthreads();
            if (tid < 128) {                       // gates layer 1
                int p = tid >> 6, b = tid & 63;
                uint64_t sg[4];
#pragma unroll
                for (int g = 0; g < 4; ++g) {
                    int pi = g * 2 + p;
                    uint64_t v = gp[(size_t)pi * B_ + b];
#pragma unroll
                    for (int ss = 1; ss < 8; ++ss)
                        addf2(v, gp[((size_t)ss * 8 + pi) * B_ + b]);
                    sg[g] = v;
                }
                float2 vi = unpk(sg[0]), vf = unpk(sg[1]);
                float2 vg = unpk(sg[2]), vo = unpk(sg[3]);
#pragma unroll
                for (int j2 = 0; j2 < 2; ++j2) {
                    int j = 2 * p + j2;
                    float gi = (j2 ? vi.y : vi.x) + bias[16 + j];
                    float gf = (j2 ? vf.y : vf.x) + bias[16 + 4 + j];
                    float gg = (j2 ? vg.y : vg.x) + bias[16 + 8 + j];
                    float go = (j2 ? vo.y : vo.x) + bias[16 + 12 + j];
                    float si = fast_sigmoid(gi);
                    float sf = fast_sigmoid(gf);
                    float so = fast_sigmoid(go);
                    float tg = fast_tanh(gg);
                    int ci = 256 + j * 64 + b;
                    float c = sf * cst[ci] + si * tg;
                    cst[ci] = c;
                    g_h2[(size_t)(r - 1) * H_ * B_ + (size_t)(j0 + j) * B_ + b]
                        = so * fast_tanh(c);
                }
            }
        }

        // =============== publish B[r-1]; wait A[r] (next round) ===========
        __syncthreads();
        if (tid == 0) {
            if (r >= 1) {
                __threadfence();
                atomicAdd(&g_cntB[r - 1], 1);
            }
            if (r < T_) {
                while (ld_acq(&g_cntA[r]) < NCTA) {}
            }
        }
        __syncthreads();
    }

    // ---- head on CTA 0 ----
    if (blockIdx.x == 0) {
        if (tid == 0) {
            while (ld_acq(&g_cntB[T_ - 1]) < NCTA) {}
        }
        __syncthreads();
        float* hv = (float*)smem;                      // [64][521]
        float* lg = (float*)(smem + OFF_LG);           // [640]
        const float* h2l = g_h2 + (size_t)(T_ - 1) * H_ * B_;
        for (int idx = tid; idx < H_ * B_; idx += NTHR) {
            int k = idx >> 6, b = idx & 63;
            hv[b * HV_STRIDE + k] = h2l[idx];
        }
        __syncthreads();
        for (int pr = s * 40; pr < s * 40 + 40; ++pr) {
            int b = pr / OUT_, o = pr % OUT_;
            float sum = 0.f;
            for (int i = lane; i < H_; i += 32)
                sum += hv[b * HV_STRIDE + i] * Wlin[(size_t)o * H_ + i];
#pragma unroll
            for (int off = 16; off; off >>= 1)
                sum += __shfl_xor_sync(0xffffffffu, sum, off);
            if (lane == 0) lg[pr] = sum + blin[o];
        }
        __syncthreads();
        if (tid < B_) {
            float m = -1e30f;
#pragma unroll
            for (int q = 0; q < OUT_; ++q) m = fmaxf(m, lg[tid * OUT_ + q]);
            float z = 0.f;
#pragma unroll
            for (int q = 0; q < OUT_; ++q) z += expf(lg[tid * OUT_ + q] - m);
            float lse = m + logf(z);
#pragma unroll
            for (int q = 0; q < OUT_; ++q)
                out[tid * OUT_ + q] = lg[tid * OUT_ + q] - lse;
        }
    }
}

extern "C" void kernel_launch(void* const* d_in, const int* in_sizes, int n_in,
                              void* d_out, int out_size) {
    const float* x    = (const float*)d_in[0];
    const float* Wih0 = (const float*)d_in[1];
    const float* Whh0 = (const float*)d_in[2];
    const float* bih0 = (const float*)d_in[3];
    const float* bhh0 = (const float*)d_in[4];
    const float* Wih1 = (const float*)d_in[5];
    const float* Whh1 = (const float*)d_in[6];
    const float* bih1 = (const float*)d_in[7];
    const float* bhh1 = (const float*)d_in[8];
    const float* Wlin = (const float*)d_in[9];
    const float* blin = (const float*)d_in[10];
    float* out = (float*)d_out;

    cudaFuncSetAttribute(lstm_kernel,
                         cudaFuncAttributeMaxDynamicSharedMemorySize,
                         (int)SMEM_BYTES);

    prep_kernel<<<T_, 256>>>(x);
    lstm_kernel<<<NCTA, NTHR, SMEM_BYTES>>>(Wih0, Whh0, bih0, bhh0,
                                            Wih1, Whh1, bih1, bhh1,
                                            Wlin, blin, out);
}